// round 2
// baseline (speedup 1.0000x reference)
#include <cuda_runtime.h>
#include <math.h>

#define BB 8
#define NNODE 1024
#define FD 128
#define GD 64
#define EC 2
#define NH 4
#define NEDGE 16384
#define L0D 256
#define ROWS (BB*NNODE)   // 8192

// ---------------- scratch (static __device__, no allocation) ----------------
__device__ float g_adj[(size_t)BB*EC*NNODE*NNODE];   // 64 MB counts
__device__ float g_Wh[(size_t)BB*EC*NH*NNODE*GD];    // 16 MB
__device__ float g_q[BB*EC*NH*NNODE];
__device__ float g_v[BB*EC*NH*NNODE];
__device__ float g_Xsum[BB*FD];
__device__ float g_Swh[BB*EC*NH*GD];
__device__ float g_Hcat[(size_t)ROWS*512];           // 16 MB
__device__ float g_T1[ROWS*FD];
__device__ float g_H2[ROWS*FD];
__device__ float g_U[ROWS*L0D];
__device__ float g_Ue[ROWS*L0D];
__device__ float g_T3[ROWS*FD];
// stats layout: [0:128) sum1 [128:256) sq1 [256:512) sum2 [512:768) sq2 [768:896) sum3 [896:1024) sq3
__device__ float g_stats[1024];

// ---------------- kernels ----------------
__global__ void k_zero() {
    size_t i = (size_t)blockIdx.x * blockDim.x + threadIdx.x;  // 4M threads, 1 float4 each
    ((float4*)g_adj)[i] = make_float4(0.f, 0.f, 0.f, 0.f);
    if (blockIdx.x == 0) { g_stats[threadIdx.x] = 0.f; g_stats[threadIdx.x + 512] = 0.f; }
}

__global__ void k_scatter(const int* __restrict__ A) {
    int idx = blockIdx.x * blockDim.x + threadIdx.x;   // 262144 edges total
    int be = idx >> 14;
    int i  = idx & (NEDGE - 1);
    int src = A[(be * 2 + 0) * NEDGE + i];
    int dst = A[(be * 2 + 1) * NEDGE + i];
    atomicAdd(&g_adj[((size_t)be * NNODE + src) * NNODE + dst], 1.0f);
}

// Wh[b,e,h,n,g] = sum_f X[b,n,f] * Ws[e, h*128+f, g]
__global__ __launch_bounds__(256) void k_wh(const float* __restrict__ X, const float* __restrict__ Ws) {
    __shared__ float sX[32 * 129];
    __shared__ float sW[64 * 64];
    int nt = blockIdx.x;   // 0..31  (n tile)
    int b = blockIdx.y, e = blockIdx.z;
    int t = threadIdx.x;
    int row = t >> 3, gb = (t & 7) * 8;
    int n0 = nt * 32;
    for (int i = t; i < 32 * 128; i += 256) {
        int r = i >> 7, f = i & 127;
        sX[r * 129 + f] = X[((size_t)b * NNODE + n0 + r) * FD + f];
    }
    for (int h = 0; h < NH; h++) {
        float acc[8] = {0,0,0,0,0,0,0,0};
        for (int fc = 0; fc < 128; fc += 64) {
            __syncthreads();
            for (int i = t; i < 64 * 64; i += 256) {
                int f = i >> 6, g = i & 63;
                sW[f * 64 + g] = Ws[((size_t)e * 512 + h * 128 + fc + f) * GD + g];
            }
            __syncthreads();
#pragma unroll
            for (int f = 0; f < 64; f++) {
                float a = sX[row * 129 + fc + f];
#pragma unroll
                for (int c = 0; c < 8; c++) acc[c] += a * sW[f * 64 + gb + c];
            }
        }
        float* dst = g_Wh + (((size_t)(b * EC + e) * NH + h) * NNODE + (n0 + row)) * GD + gb;
#pragma unroll
        for (int c = 0; c < 8; c++) dst[c] = acc[c];
    }
}

// q[b,e,h,n] = X[b,n,:]·Wq[e,h,:],  same for v.  One warp per (b,n).
__global__ void k_qv(const float* __restrict__ X, const float* __restrict__ Wq,
                     const float* __restrict__ Wv) {
    int wid = blockIdx.x * 8 + (threadIdx.x >> 5);   // 0..8191
    int lane = threadIdx.x & 31;
    const float* xr = X + (size_t)wid * FD;
    float x0 = xr[lane * 4], x1 = xr[lane * 4 + 1], x2 = xr[lane * 4 + 2], x3 = xr[lane * 4 + 3];
    int b = wid >> 10, n = wid & 1023;
    for (int eh = 0; eh < EC * NH; eh++) {
        int e = eh >> 2, h = eh & 3;
        const float* wq = Wq + (e * 512 + h * 128);
        const float* wv = Wv + (e * 512 + h * 128);
        float pq = x0 * wq[lane*4] + x1 * wq[lane*4+1] + x2 * wq[lane*4+2] + x3 * wq[lane*4+3];
        float pv = x0 * wv[lane*4] + x1 * wv[lane*4+1] + x2 * wv[lane*4+2] + x3 * wv[lane*4+3];
        for (int off = 16; off; off >>= 1) {
            pq += __shfl_down_sync(0xffffffffu, pq, off);
            pv += __shfl_down_sync(0xffffffffu, pv, off);
        }
        if (lane == 0) {
            int idx = ((b * EC + e) * NH + h) * NNODE + n;
            g_q[idx] = pq; g_v[idx] = pv;
        }
    }
}

__global__ void k_xsum(const float* __restrict__ X) {
    int b = blockIdx.x, f = threadIdx.x;
    float s = 0.f;
    for (int n = 0; n < NNODE; n++) s += X[((size_t)b * NNODE + n) * FD + f];
    g_Xsum[b * FD + f] = s;
}

// Swh[b,e,h,g] = sum_f Xsum[b,f] * Ws[e,h*128+f,g]
__global__ void k_swh(const float* __restrict__ Ws) {
    int beh = blockIdx.x;          // b*8 + e*4 + h
    int g = threadIdx.x;
    int b = beh >> 3, e = (beh >> 2) & 1, h = beh & 3;
    float s = 0.f;
    for (int f = 0; f < FD; f++)
        s += g_Xsum[b * FD + f] * Ws[((size_t)e * 512 + h * 128 + f) * GD + g];
    g_Swh[beh * GD + g] = s;
}

// Sparse attention aggregation per (b,n). Threads: (h,g) = 4*64.
__global__ __launch_bounds__(256) void k_attn() {
    __shared__ int s_m[1024];
    __shared__ float s_c[1024];
    __shared__ int s_cnt;
    int bn = blockIdx.x;
    int b = bn >> 10, n = bn & 1023;
    int t = threadIdx.x;
    int h = t >> 6, g = t & 63;
    for (int e = 0; e < EC; e++) {
        if (t == 0) s_cnt = 0;
        __syncthreads();
        const float* arow = g_adj + ((size_t)(b * EC + e) * NNODE + n) * NNODE;
        for (int m = t; m < NNODE; m += 256) {
            float c = arow[m];
            if (c != 0.f) { int idx = atomicAdd(&s_cnt, 1); s_m[idx] = m; s_c[idx] = c; }
        }
        __syncthreads();
        int beh = (b * EC + e) * NH + h;
        float qn = g_q[beh * NNODE + n];
        const float* vb = g_v + beh * NNODE;
        const float* Whb = g_Wh + (size_t)beh * NNODE * GD;
        float num = 0.f, den = 0.f;
        int cnt = s_cnt;
        for (int j = 0; j < cnt; j++) {
            int m = s_m[j]; float c = s_c[j];
            float s = qn * vb[m] * c;
            float l = s >= 0.f ? s : 0.01f * s;
            float w = expf(l) - 1.f;
            den += w;
            num += w * Whb[m * GD + g];
        }
        float out = (g_Swh[beh * GD + g] + num) / (1024.f + den);
        g_Hcat[(size_t)bn * 512 + h * 128 + e * 64 + g] = out;
        __syncthreads();
    }
}

// Generic smem-tiled f32 GEMM  C[r,o] = sum_k A[r,k]*W[o,k]  with per-phase epilogue.
// PH0: A=g_Hcat K=512 NC=128 -> T1 = 0.5*relu + 0.5*X
// PH1: A=g_H2   K=128 NC=256 -> U
// PH2: A=g_Ue   K=256 NC=128 -> T3 = acc + H2
template <int PH>
__global__ __launch_bounds__(256) void k_gemm(const float* __restrict__ Wm,
                                              const float* __restrict__ X) {
    constexpr int K  = (PH == 0) ? 512 : (PH == 1) ? 128 : 256;
    constexpr int NC = (PH == 1) ? 256 : 128;
    const float* Amat = (PH == 0) ? g_Hcat : (PH == 1) ? g_H2 : g_Ue;
    float* Cm         = (PH == 0) ? g_T1   : (PH == 1) ? g_U  : g_T3;
    __shared__ float sA[32 * 65];
    __shared__ float sW[64 * 65];
    int r0 = blockIdx.x * 32, c0 = blockIdx.y * 64;
    int t = threadIdx.x;
    int row = t >> 3, cb = (t & 7) * 8;
    float acc[8] = {0,0,0,0,0,0,0,0};
    for (int kc = 0; kc < K; kc += 64) {
        for (int i = t; i < 2048; i += 256) {
            int r = i >> 6, k = i & 63;
            sA[r * 65 + k] = Amat[(size_t)(r0 + r) * K + kc + k];
        }
        for (int i = t; i < 4096; i += 256) {
            int c = i >> 6, k = i & 63;
            sW[k * 65 + c] = Wm[(size_t)(c0 + c) * K + kc + k];
        }
        __syncthreads();
#pragma unroll
        for (int k = 0; k < 64; k++) {
            float a = sA[row * 65 + k];
#pragma unroll
            for (int c = 0; c < 8; c++) acc[c] += a * sW[k * 65 + cb + c];
        }
        __syncthreads();
    }
    size_t rg = r0 + row;
#pragma unroll
    for (int c = 0; c < 8; c++) {
        int col = c0 + cb + c;
        float v = acc[c];
        if (PH == 0) v = 0.5f * fmaxf(v, 0.f) + 0.5f * X[rg * FD + col];
        if (PH == 2) v = v + g_H2[rg * FD + col];
        Cm[rg * NC + col] = v;
    }
}

// Column sum / sumsq over 8192 rows. PH0: T1/128 -> stats[0,128]; PH1: U/256 -> [256,512]; PH2: T3/128 -> [768,896]
template <int PH>
__global__ void k_colreduce() {
    constexpr int C = (PH == 1) ? 256 : 128;
    const float* src = (PH == 0) ? g_T1 : (PH == 1) ? g_U : g_T3;
    float* sum = g_stats + ((PH == 0) ? 0 : (PH == 1) ? 256 : 768);
    float* sq  = g_stats + ((PH == 0) ? 128 : (PH == 1) ? 512 : 896);
    __shared__ float sh[512];
    int t = threadIdx.x;
    int r0 = blockIdx.x * 128;
    if (C == 128) {
        int col = t & 127, rl = t >> 7;
        float s = 0.f, q = 0.f;
        for (int r = rl; r < 128; r += 2) {
            float v = src[(size_t)(r0 + r) * 128 + col];
            s += v; q += v * v;
        }
        sh[t] = s; sh[256 + t] = q;
        __syncthreads();
        if (t < 128) {
            atomicAdd(&sum[t], sh[t] + sh[t + 128]);
            atomicAdd(&sq[t],  sh[256 + t] + sh[384 + t]);
        }
    } else {
        int col = t;
        float s = 0.f, q = 0.f;
        for (int r = 0; r < 128; r++) {
            float v = src[(size_t)(r0 + r) * 256 + col];
            s += v; q += v * v;
        }
        atomicAdd(&sum[col], s);
        atomicAdd(&sq[col], q);
    }
}

__global__ void k_norm1() {  // H2 = bn(T1)
    int i = blockIdx.x * blockDim.x + threadIdx.x;
    int col = i & 127;
    float mu = g_stats[col] * (1.f / 8192.f);
    float var = g_stats[128 + col] * (1.f / 8192.f) - mu * mu;
    float rs = rsqrtf(var + 1e-5f);
    g_H2[i] = (g_T1[i] - mu) * rs;
}

__global__ void k_norm2() {  // Ue = elu(bn(U))
    int i = blockIdx.x * blockDim.x + threadIdx.x;
    int col = i & 255;
    float mu = g_stats[256 + col] * (1.f / 8192.f);
    float var = g_stats[512 + col] * (1.f / 8192.f) - mu * mu;
    float rs = rsqrtf(var + 1e-5f);
    float x = (g_U[i] - mu) * rs;
    g_Ue[i] = x > 0.f ? x : expm1f(x);
}

__global__ void k_norm3(float* __restrict__ out) {  // out = bn(T3)
    int i = blockIdx.x * blockDim.x + threadIdx.x;
    int col = i & 127;
    float mu = g_stats[768 + col] * (1.f / 8192.f);
    float var = g_stats[896 + col] * (1.f / 8192.f) - mu * mu;
    float rs = rsqrtf(var + 1e-5f);
    out[i] = (g_T3[i] - mu) * rs;
}

// ---------------- launch ----------------
extern "C" void kernel_launch(void* const* d_in, const int* in_sizes, int n_in,
                              void* d_out, int out_size) {
    const int*   A    = (const int*)d_in[0];
    const float* X    = (const float*)d_in[1];
    const float* Ws   = (const float*)d_in[2];
    const float* Wq   = (const float*)d_in[3];
    const float* Wv   = (const float*)d_in[4];
    const float* Wemb = (const float*)d_in[5];
    const float* Wl0  = (const float*)d_in[6];
    const float* Wl1  = (const float*)d_in[7];
    float* out = (float*)d_out;

    k_zero<<<8192, 512>>>();
    k_scatter<<<1024, 256>>>(A);
    k_wh<<<dim3(32, 8, 2), 256>>>(X, Ws);
    k_qv<<<1024, 256>>>(X, Wq, Wv);
    k_xsum<<<8, 128>>>(X);
    k_swh<<<64, 64>>>(Ws);
    k_attn<<<8192, 256>>>();
    k_gemm<0><<<dim3(256, 2), 256>>>(Wemb, X);
    k_colreduce<0><<<64, 256>>>();
    k_norm1<<<4096, 256>>>();
    k_gemm<1><<<dim3(256, 4), 256>>>(Wl0, nullptr);
    k_colreduce<1><<<64, 256>>>();
    k_norm2<<<8192, 256>>>();
    k_gemm<2><<<dim3(256, 2), 256>>>(Wl1, nullptr);
    k_colreduce<2><<<64, 256>>>();
    k_norm3<<<4096, 256>>>(out);
}

// round 3
// speedup vs baseline: 2.3346x; 2.3346x over previous
#include <cuda_runtime.h>
#include <math.h>

#define BB 8
#define NNODE 1024
#define FD 128
#define GD 64
#define EC 2
#define NH 4
#define NEDGE 16384
#define L0D 256
#define ROWS (BB*NNODE)   // 8192

// ---------------- scratch ----------------
__device__ float g_adj[(size_t)BB*EC*NNODE*NNODE];   // 64 MB counts
__device__ float g_Wh[(size_t)ROWS*512];             // [bn][e*256+h*64+g] 16MB
__device__ float g_qv[ROWS*16];                      // [bn][ q:e*4+h | 8+v ]
__device__ float g_W2[512*128];                      // packed Ws  [col][f]
__device__ float g_Wqv[16*128];                      // packed Wq/Wv [col][f]
__device__ float g_Xsum[BB*FD];
__device__ float g_Swh[BB*512];                      // [b][col]
__device__ float g_Hcat[(size_t)ROWS*512];
__device__ float g_T1[ROWS*FD];
__device__ float g_H2[ROWS*FD];
__device__ float g_U[ROWS*L0D];
__device__ float g_Ue[ROWS*L0D];
__device__ float g_T3[ROWS*FD];
// stats: [0:128) sum1 [128:256) sq1 [256:512) sum2 [512:768) sq2 [768:896) sum3 [896:1024) sq3
__device__ float g_stats[1024];

// ---------------- small setup kernels ----------------
__global__ void k_zero() {
    size_t i = (size_t)blockIdx.x * blockDim.x + threadIdx.x;
    ((float4*)g_adj)[i] = make_float4(0.f, 0.f, 0.f, 0.f);
    if (blockIdx.x == 0) { g_stats[threadIdx.x] = 0.f; g_stats[threadIdx.x + 512] = 0.f; }
}

__global__ void k_scatter(const int* __restrict__ A) {
    int idx = blockIdx.x * blockDim.x + threadIdx.x;
    int be = idx >> 14;
    int i  = idx & (NEDGE - 1);
    int src = A[(be * 2 + 0) * NEDGE + i];
    int dst = A[(be * 2 + 1) * NEDGE + i];
    atomicAdd(&g_adj[((size_t)be * NNODE + src) * NNODE + dst], 1.0f);
}

// pack W2[col][f] (col = e*256+h*64+g) and Wqv[col][f]
__global__ void k_pack(const float* __restrict__ Ws, const float* __restrict__ Wq,
                       const float* __restrict__ Wv) {
    int idx = blockIdx.x * blockDim.x + threadIdx.x;
    if (idx < 512 * 128) {
        int col = idx >> 7, f = idx & 127;
        int e = col >> 8, rem = col & 255, h = rem >> 6, g = rem & 63;
        g_W2[idx] = Ws[((size_t)e * 512 + h * 128 + f) * GD + g];
    } else if (idx < 512 * 128 + 16 * 128) {
        int i2 = idx - 512 * 128;
        int col = i2 >> 7, f = i2 & 127;
        if (col < 8) {
            int e = col >> 2, h = col & 3;
            g_Wqv[i2] = Wq[e * 512 + h * 128 + f];
        } else {
            int c = col - 8, e = c >> 2, h = c & 3;
            g_Wqv[i2] = Wv[e * 512 + h * 128 + f];
        }
    }
}

__global__ void k_xsum(const float* __restrict__ X) {
    __shared__ float sh[512];
    int b = blockIdx.x, t = threadIdx.x, f = t & 127, nl = t >> 7;
    float s = 0.f;
    for (int n = nl; n < NNODE; n += 4) s += X[((size_t)b * NNODE + n) * FD + f];
    sh[t] = s;
    __syncthreads();
    if (t < 128) g_Xsum[b * FD + t] = sh[t] + sh[t + 128] + sh[t + 256] + sh[t + 384];
}

__global__ void k_swh() {
    __shared__ float sx[128];
    int b = blockIdx.x, col = threadIdx.x;
    if (col < 128) sx[col] = g_Xsum[b * FD + col];
    __syncthreads();
    float s = 0.f;
#pragma unroll 4
    for (int f = 0; f < 128; f++) s += sx[f] * g_W2[col * 128 + f];
    g_Swh[b * 512 + col] = s;
}

// qv[bn][0..15]
__global__ __launch_bounds__(256) void k_qv2(const float* __restrict__ X) {
    __shared__ float sX[64][129];
    __shared__ float sW[16][128];
    int t = threadIdx.x;
    int row0 = blockIdx.x * 64;
    for (int i = t; i < 64 * 128; i += 256) {
        int r = i >> 7, f = i & 127;
        sX[r][f] = X[(size_t)(row0 + r) * FD + f];
    }
    for (int i = t; i < 16 * 128; i += 256) sW[i >> 7][i & 127] = g_Wqv[i];
    __syncthreads();
    int row = t & 63, cg = (t >> 6) * 4;
    float acc[4] = {0.f, 0.f, 0.f, 0.f};
#pragma unroll 4
    for (int f = 0; f < 128; f++) {
        float a = sX[row][f];
#pragma unroll
        for (int c = 0; c < 4; c++) acc[c] += a * sW[cg + c][f];
    }
#pragma unroll
    for (int c = 0; c < 4; c++) g_qv[(size_t)(row0 + row) * 16 + cg + c] = acc[c];
}

// ---------------- register-blocked GEMM: C[8192][NC] = A[8192][K] @ W[NC][K]^T ----------------
// PH0: A=X      W=g_W2   C=g_Wh   K=128 NC=512 plain
// PH1: A=g_Hcat W=Wemb   C=g_T1   K=512 NC=128  0.5*relu+0.5*X
// PH2: A=g_H2   W=Wl0    C=g_U    K=128 NC=256 plain
// PH3: A=g_Ue   W=Wl1    C=g_T3   K=256 NC=128  +g_H2
template <int PH>
__global__ __launch_bounds__(256) void k_gemm(const float* __restrict__ ext_w,
                                              const float* __restrict__ ext_x) {
    constexpr int K  = (PH == 1) ? 512 : (PH == 3) ? 256 : 128;
    constexpr int NC = (PH == 0) ? 512 : (PH == 2) ? 256 : 128;
    const float* Am = (PH == 0) ? ext_x : (PH == 1) ? g_Hcat : (PH == 2) ? g_H2 : g_Ue;
    const float* Wm = (PH == 0) ? g_W2 : ext_w;
    float* Cm       = (PH == 0) ? g_Wh : (PH == 1) ? g_T1 : (PH == 2) ? g_U : g_T3;

    __shared__ float sA[32][68];
    __shared__ float sB[32][68];
    int t = threadIdx.x;
    int r0 = blockIdx.x * 64, c0 = blockIdx.y * 64;
    int tx = t & 15, ty = t >> 4;
    int kl = t & 31, il = t >> 5;
    float acc[4][4] = {};
    for (int kc = 0; kc < K; kc += 32) {
#pragma unroll
        for (int p = 0; p < 8; p++) {
            int i = il + p * 8;
            sA[kl][i] = Am[(size_t)(r0 + i) * K + kc + kl];
            sB[kl][i] = Wm[(size_t)(c0 + i) * K + kc + kl];
        }
        __syncthreads();
#pragma unroll
        for (int k = 0; k < 32; k++) {
            float4 a = *(const float4*)&sA[k][ty * 4];
            float4 b = *(const float4*)&sB[k][tx * 4];
            acc[0][0] += a.x * b.x; acc[0][1] += a.x * b.y; acc[0][2] += a.x * b.z; acc[0][3] += a.x * b.w;
            acc[1][0] += a.y * b.x; acc[1][1] += a.y * b.y; acc[1][2] += a.y * b.z; acc[1][3] += a.y * b.w;
            acc[2][0] += a.z * b.x; acc[2][1] += a.z * b.y; acc[2][2] += a.z * b.z; acc[2][3] += a.z * b.w;
            acc[3][0] += a.w * b.x; acc[3][1] += a.w * b.y; acc[3][2] += a.w * b.z; acc[3][3] += a.w * b.w;
        }
        __syncthreads();
    }
#pragma unroll
    for (int r = 0; r < 4; r++) {
        size_t rg = r0 + ty * 4 + r;
        int cg = c0 + tx * 4;
        float4 v = make_float4(acc[r][0], acc[r][1], acc[r][2], acc[r][3]);
        if (PH == 1) {
            float4 x = *(const float4*)&ext_x[rg * FD + cg];
            v.x = 0.5f * fmaxf(v.x, 0.f) + 0.5f * x.x;
            v.y = 0.5f * fmaxf(v.y, 0.f) + 0.5f * x.y;
            v.z = 0.5f * fmaxf(v.z, 0.f) + 0.5f * x.z;
            v.w = 0.5f * fmaxf(v.w, 0.f) + 0.5f * x.w;
        }
        if (PH == 3) {
            float4 x = *(const float4*)&g_H2[rg * FD + cg];
            v.x += x.x; v.y += x.y; v.z += x.z; v.w += x.w;
        }
        *(float4*)&Cm[rg * NC + cg] = v;
    }
}

// ---------------- sparse attention ----------------
__global__ __launch_bounds__(256) void k_attn() {
    __shared__ int s_m[1024];
    __shared__ float s_c[1024];
    __shared__ float s_w[1024][4];
    __shared__ int s_cnt;
    int bn = blockIdx.x;
    int b = bn >> 10, n = bn & 1023;
    int t = threadIdx.x;
    int h = t >> 6, g = t & 63;
    for (int e = 0; e < EC; e++) {
        if (t == 0) s_cnt = 0;
        __syncthreads();
        const float* arow = g_adj + ((size_t)(b * EC + e) * NNODE + n) * NNODE;
        for (int m = t; m < NNODE; m += 256) {
            float c = arow[m];
            if (c != 0.f) { int idx = atomicAdd(&s_cnt, 1); s_m[idx] = m; s_c[idx] = c; }
        }
        __syncthreads();
        int cnt = s_cnt;
        // parallel weight compute: one (j,h) per thread slot
        for (int jj = t; jj < cnt * 4; jj += 256) {
            int j = jj >> 2, hh = jj & 3;
            int m = s_m[j];
            float qn = g_qv[(size_t)bn * 16 + e * 4 + hh];
            float vm = g_qv[((size_t)b * NNODE + m) * 16 + 8 + e * 4 + hh];
            float s = qn * vm * s_c[j];
            float l = s >= 0.f ? s : 0.01f * s;
            s_w[j][hh] = expf(l) - 1.f;
        }
        __syncthreads();
        const float* Whb = g_Wh + (size_t)b * NNODE * 512 + e * 256 + h * 64 + g;
        float num = 0.f, den = 0.f;
        int j = 0;
        for (; j + 4 <= cnt; j += 4) {
            float w0 = s_w[j][h], w1 = s_w[j + 1][h], w2 = s_w[j + 2][h], w3 = s_w[j + 3][h];
            float x0 = __ldg(&Whb[(size_t)s_m[j] * 512]);
            float x1 = __ldg(&Whb[(size_t)s_m[j + 1] * 512]);
            float x2 = __ldg(&Whb[(size_t)s_m[j + 2] * 512]);
            float x3 = __ldg(&Whb[(size_t)s_m[j + 3] * 512]);
            num += w0 * x0 + w1 * x1 + w2 * x2 + w3 * x3;
            den += w0 + w1 + w2 + w3;
        }
        for (; j < cnt; j++) {
            float w = s_w[j][h];
            num += w * __ldg(&Whb[(size_t)s_m[j] * 512]);
            den += w;
        }
        float out = (g_Swh[b * 512 + e * 256 + h * 64 + g] + num) / (1024.f + den);
        g_Hcat[(size_t)bn * 512 + h * 128 + e * 64 + g] = out;
        __syncthreads();
    }
}

// ---------------- BN reductions / normalizations ----------------
template <int PH>
__global__ void k_colreduce() {
    constexpr int C = (PH == 1) ? 256 : 128;
    const float* src = (PH == 0) ? g_T1 : (PH == 1) ? g_U : g_T3;
    float* sum = g_stats + ((PH == 0) ? 0 : (PH == 1) ? 256 : 768);
    float* sq  = g_stats + ((PH == 0) ? 128 : (PH == 1) ? 512 : 896);
    __shared__ float sh[512];
    int t = threadIdx.x;
    int r0 = blockIdx.x * 128;
    if (C == 128) {
        int col = t & 127, rl = t >> 7;
        float s = 0.f, q = 0.f;
        for (int r = rl; r < 128; r += 2) {
            float v = src[(size_t)(r0 + r) * 128 + col];
            s += v; q += v * v;
        }
        sh[t] = s; sh[256 + t] = q;
        __syncthreads();
        if (t < 128) {
            atomicAdd(&sum[t], sh[t] + sh[t + 128]);
            atomicAdd(&sq[t],  sh[256 + t] + sh[384 + t]);
        }
    } else {
        int col = t;
        float s = 0.f, q = 0.f;
        for (int r = 0; r < 128; r++) {
            float v = src[(size_t)(r0 + r) * 256 + col];
            s += v; q += v * v;
        }
        atomicAdd(&sum[col], s);
        atomicAdd(&sq[col], q);
    }
}

__global__ void k_norm1() {
    int i = blockIdx.x * blockDim.x + threadIdx.x;
    int col = i & 127;
    float mu = g_stats[col] * (1.f / 8192.f);
    float var = g_stats[128 + col] * (1.f / 8192.f) - mu * mu;
    float rs = rsqrtf(var + 1e-5f);
    g_H2[i] = (g_T1[i] - mu) * rs;
}

__global__ void k_norm2() {
    int i = blockIdx.x * blockDim.x + threadIdx.x;
    int col = i & 255;
    float mu = g_stats[256 + col] * (1.f / 8192.f);
    float var = g_stats[512 + col] * (1.f / 8192.f) - mu * mu;
    float rs = rsqrtf(var + 1e-5f);
    float x = (g_U[i] - mu) * rs;
    g_Ue[i] = x > 0.f ? x : expm1f(x);
}

__global__ void k_norm3(float* __restrict__ out) {
    int i = blockIdx.x * blockDim.x + threadIdx.x;
    int col = i & 127;
    float mu = g_stats[768 + col] * (1.f / 8192.f);
    float var = g_stats[896 + col] * (1.f / 8192.f) - mu * mu;
    float rs = rsqrtf(var + 1e-5f);
    out[i] = (g_T3[i] - mu) * rs;
}

// ---------------- launch ----------------
extern "C" void kernel_launch(void* const* d_in, const int* in_sizes, int n_in,
                              void* d_out, int out_size) {
    const int*   A    = (const int*)d_in[0];
    const float* X    = (const float*)d_in[1];
    const float* Ws   = (const float*)d_in[2];
    const float* Wq   = (const float*)d_in[3];
    const float* Wv   = (const float*)d_in[4];
    const float* Wemb = (const float*)d_in[5];
    const float* Wl0  = (const float*)d_in[6];
    const float* Wl1  = (const float*)d_in[7];
    float* out = (float*)d_out;

    k_zero<<<8192, 512>>>();
    k_scatter<<<1024, 256>>>(A);
    k_pack<<<66, 1024>>>(Ws, Wq, Wv);
    k_gemm<0><<<dim3(128, 8), 256>>>(nullptr, X);     // Wh
    k_qv2<<<128, 256>>>(X);
    k_xsum<<<8, 512>>>(X);
    k_swh<<<8, 512>>>();
    k_attn<<<8192, 256>>>();
    k_gemm<1><<<dim3(128, 2), 256>>>(Wemb, X);        // T1
    k_colreduce<0><<<64, 256>>>();
    k_norm1<<<4096, 256>>>();
    k_gemm<2><<<dim3(128, 4), 256>>>(Wl0, nullptr);   // U
    k_colreduce<1><<<64, 256>>>();
    k_norm2<<<8192, 256>>>();
    k_gemm<3><<<dim3(128, 2), 256>>>(Wl1, nullptr);   // T3
    k_colreduce<2><<<64, 256>>>();
    k_norm3<<<4096, 256>>>(out);
}